// round 16
// baseline (speedup 1.0000x reference)
#include <cuda_runtime.h>
#include <cuda_fp16.h>
#include <cstdint>

// ============================================================
// IVFBook: dist = ||c||^2 - 2 x.c ; codes = argmin ; out = C[codes]
// B=4096, D=256, K=65536.
// Phase 1: 1-pass fp16 mma.sync approx GEMM. 256 threads, warp tile
//          32x64 (crossbar 24KB/k16 < 256cyc HMMA). A-resident smem,
//          B 8-stage cp.async pipeline, sync every 4 chunks, csq in
//          smem, sync-free per-warp epilogue -> g_lmin2[row][tile][wn].
// Phase 2: per-row exact fp32 rerank of tiles within margin of the
//          global approx min (provably safe bound), coalesced.
// Output float32: [B*D quantized x][B codes-as-float]
// ============================================================

#define D_DIM 256
#define BMT 128          // CTA M tile
#define BNT 128          // N tile
#define KCH 64           // K chunk (fp16 elems) = 128B row
#define NCHT 4           // chunks per n-tile (D_DIM/KCH)
#define THREADS 256
#define ROWB 144         // B smem row stride (bytes): 36 words == 4 mod 32
#define ROWA 528         // A smem row stride (bytes)
#define NT_TILES 512     // K / BNT
#define NGT 16           // n-tiles per CTA
#define TOTCH (NGT * NCHT)  // 64 chunks per CTA
#define M_MARGIN 0.75f

#define A_BYTES (BMT * ROWA)      // 67584
#define B_STAGE (128 * ROWB)      // 18432
#define NSTAGE 8
#define CSQ_OFF (A_BYTES + NSTAGE * B_STAGE)          // 215040
#define SMEM_DYN (CSQ_OFF + NGT * BNT * 4)            // +8192 = 223232

__device__ unsigned long long g_best[4096];
__device__ unsigned g_lmin2[4096 * NT_TILES * 2];   // 16MB: 2 warp-partials/tile
__device__ float g_csq[65536];
__device__ __half g_c_hi[65536 * 256];
__device__ __half g_x_hi[4096 * 256];

__device__ __forceinline__ unsigned enc_f32(float f) {
    unsigned u = __float_as_uint(f);
    return (u & 0x80000000u) ? ~u : (u | 0x80000000u);
}
__device__ __forceinline__ float dec_f32(unsigned u) {
    unsigned v = (u & 0x80000000u) ? (u & 0x7FFFFFFFu) : ~u;
    return __uint_as_float(v);
}
__device__ __forceinline__ uint32_t smem_u32(const void* p) {
    uint32_t a;
    asm("{ .reg .u64 t; cvta.to.shared.u64 t, %1; cvt.u32.u64 %0, t; }"
        : "=r"(a) : "l"(p));
    return a;
}

#define LDSM4(r0, r1, r2, r3, addr) \
    asm volatile("ldmatrix.sync.aligned.m8n8.x4.shared.b16 {%0,%1,%2,%3}, [%4];" \
                 : "=r"(r0), "=r"(r1), "=r"(r2), "=r"(r3) : "r"(addr))

#define MMA_F16(d, a, b0, b1) \
    asm volatile( \
        "mma.sync.aligned.m16n8k16.row.col.f32.f16.f16.f32 " \
        "{%0,%1,%2,%3},{%4,%5,%6,%7},{%8,%9},{%0,%1,%2,%3};" \
        : "+f"((d)[0]), "+f"((d)[1]), "+f"((d)[2]), "+f"((d)[3]) \
        : "r"((a)[0]), "r"((a)[1]), "r"((a)[2]), "r"((a)[3]), \
          "r"(b0), "r"(b1))

#define CP16(dst, src) \
    asm volatile("cp.async.cg.shared.global [%0], [%1], 16;" \
                 :: "r"(dst), "l"(src) : "memory")
#define CP_COMMIT() asm volatile("cp.async.commit_group;" ::: "memory")
#define CP_WAIT3()  asm volatile("cp.async.wait_group 3;" ::: "memory")

// 8 floats -> 8 fp16
__device__ __forceinline__ uint4 pack8(float4 v0, float4 v1) {
    float f[8] = {v0.x, v0.y, v0.z, v0.w, v1.x, v1.y, v1.z, v1.w};
    unsigned hw[4];
    #pragma unroll
    for (int i = 0; i < 4; ++i) {
        __half h0 = __float2half_rn(f[2 * i]);
        __half h1 = __float2half_rn(f[2 * i + 1]);
        hw[i] = ((unsigned)__half_as_ushort(h1) << 16) | __half_as_ushort(h0);
    }
    return make_uint4(hw[0], hw[1], hw[2], hw[3]);
}

// ---------------- split centroids (hi plane) + csq ----------------
__global__ void split_c_kernel(const float* __restrict__ C) {
    int row = blockIdx.x * 8 + (threadIdx.x >> 5);
    int lane = threadIdx.x & 31;
    const float4* p = (const float4*)(C + (size_t)row * D_DIM + lane * 8);
    float4 v0 = p[0], v1 = p[1];
    *(uint4*)(g_c_hi + (size_t)row * D_DIM + lane * 8) = pack8(v0, v1);
    float s = v0.x * v0.x + v0.y * v0.y + v0.z * v0.z + v0.w * v0.w
            + v1.x * v1.x + v1.y * v1.y + v1.z * v1.z + v1.w * v1.w;
    #pragma unroll
    for (int off = 16; off > 0; off >>= 1)
        s += __shfl_xor_sync(0xFFFFFFFFu, s, off);
    if (lane == 0) g_csq[row] = s;
}

// ---------------- split x (hi plane) ----------------
__global__ void split_x_kernel(const float* __restrict__ X) {
    int row = blockIdx.x * 8 + (threadIdx.x >> 5);
    int lane = threadIdx.x & 31;
    const float4* p = (const float4*)(X + (size_t)row * D_DIM + lane * 8);
    *(uint4*)(g_x_hi + (size_t)row * D_DIM + lane * 8) = pack8(p[0], p[1]);
}

// ---------------- Phase 1: 1-pass approx GEMM, warp tile 32x64 ----------------
__global__ void __launch_bounds__(THREADS, 1) gemm_approx_mma(int dummy) {
    extern __shared__ __align__(16) unsigned char smraw[];

    const int tid = threadIdx.x;
    const int lane = tid & 31;
    const int wid = tid >> 5;       // 0..7
    const int wm = wid >> 1;        // 0..3 : m32 group
    const int wn = wid & 1;         // 0..1 : n64 group
    const int mt_idx = blockIdx.x & 31;
    const int ng = blockIdx.x >> 5;             // 0..31
    const int m0 = mt_idx * BMT;
    const int ntile0 = ng * NGT;

    const uint32_t sbA = smem_u32(smraw);
    const uint32_t sbB = sbA + A_BYTES;
    const uint32_t sbQ = sbA + CSQ_OFF;
    const float* cqs = (const float*)(smraw + CSQ_OFF);   // 2048 floats

    const int lrow = tid >> 1;          // 0..127 (B rows)
    const int lhalf = tid & 1;          // 64B half of the 128B row

    // ---- B chunk issue (four CP16 per thread: 128B per row) ----
    #define ISSUE_B(cidx) do { \
        const int _j = (cidx) >> 2, _kc = (cidx) & 3; \
        const __half* _src = g_c_hi + \
            (size_t)((ntile0 + _j) * BNT + lrow) * D_DIM + _kc * KCH + lhalf * 32; \
        const uint32_t _dst = sbB + \
            (uint32_t)(((cidx) % NSTAGE) * B_STAGE + lrow * ROWB + lhalf * 64); \
        CP16(_dst, _src);           CP16(_dst + 16, _src + 8); \
        CP16(_dst + 32, _src + 16); CP16(_dst + 48, _src + 24); \
        CP_COMMIT(); \
    } while (0)

    // ---- group 0: A resident copy + csq + chunk 0 ----
    {
        const int arow = tid >> 1;          // 0..127
        const int ahalf = (tid & 1) * 16;   // 16 x 16B segments per row half
        const __half* aSrc = g_x_hi + (size_t)(m0 + arow) * D_DIM + ahalf * 8;
        const uint32_t dA = sbA + (uint32_t)(arow * ROWA + ahalf * 16);
        #pragma unroll
        for (int s = 0; s < 16; ++s)
            CP16(dA + s * 16, aSrc + s * 8);
        CP16(sbQ + tid * 32, g_csq + ntile0 * BNT + tid * 8);
        CP16(sbQ + tid * 32 + 16, g_csq + ntile0 * BNT + tid * 8 + 4);
        // chunk 0 into stage 0 (same commit group)
        const __half* b0 = g_c_hi + (size_t)(ntile0 * BNT + lrow) * D_DIM + lhalf * 32;
        const uint32_t d0 = sbB + (uint32_t)(lrow * ROWB + lhalf * 64);
        CP16(d0, b0);           CP16(d0 + 16, b0 + 8);
        CP16(d0 + 32, b0 + 16); CP16(d0 + 48, b0 + 24);
        CP_COMMIT();
    }
    ISSUE_B(1); ISSUE_B(2); ISSUE_B(3);

    // ---- ldmatrix per-lane addresses (validated mapping; wn*64) ----
    const uint32_t aRow = (uint32_t)((wm * 32 + (lane & 15)) * ROWA);
    const uint32_t aK   = (lane & 16) ? 16u : 0u;
    const uint32_t bRow = (uint32_t)((wn * 64 + (lane & 7) + ((lane & 16) >> 1)) * ROWB);
    const uint32_t bK   = (lane & 8) ? 16u : 0u;

    float acc[2][8][4];
    #pragma unroll
    for (int i = 0; i < 2; ++i)
        #pragma unroll
        for (int j = 0; j < 8; ++j)
            #pragma unroll
            for (int c = 0; c < 4; ++c) acc[i][j][c] = 0.0f;

    for (int cidx = 0; cidx < TOTCH; ++cidx) {
        CP_WAIT3();                       // chunk cidx complete
        if ((cidx & 3) == 0) __syncthreads();   // stage-reuse fence, every 4
        if (cidx + 4 < TOTCH) ISSUE_B(cidx + 4); else CP_COMMIT();

        const int kc = cidx & 3;
        const uint32_t stgB = sbB + (uint32_t)((cidx % NSTAGE) * B_STAGE);
        #pragma unroll
        for (int ks = 0; ks < 4; ++ks) {         // four k16 steps per chunk
            const uint32_t kBB = (uint32_t)(ks * 32);
            const uint32_t kBA = (uint32_t)(kc * 128 + ks * 32);
            unsigned ah[2][4], bh[4][4];
            #pragma unroll
            for (int mt = 0; mt < 2; ++mt) {
                uint32_t a = sbA + aRow + (uint32_t)(mt * 16 * ROWA) + kBA + aK;
                LDSM4(ah[mt][0], ah[mt][1], ah[mt][2], ah[mt][3], a);
            }
            #pragma unroll
            for (int np = 0; np < 4; ++np) {
                uint32_t b = stgB + bRow + (uint32_t)(np * 16 * ROWB) + kBB + bK;
                LDSM4(bh[np][0], bh[np][1], bh[np][2], bh[np][3], b);
            }
            #pragma unroll
            for (int mt = 0; mt < 2; ++mt)
                #pragma unroll
                for (int nt = 0; nt < 8; ++nt) {
                    const int np = nt >> 1, r = (nt & 1) * 2;
                    MMA_F16(acc[mt][nt], ah[mt], bh[np][r], bh[np][r + 1]);
                }
        }

        if (kc == NCHT - 1) {
            // ---- sync-free epilogue: per-warp min over 64 cols -> g_lmin2 ----
            const int tileIdx = cidx >> 2;
            const int ntile = ntile0 + tileIdx;
            const float* cq = cqs + tileIdx * BNT;
            #pragma unroll
            for (int mt = 0; mt < 2; ++mt) {
                #pragma unroll
                for (int half = 0; half < 2; ++half) {
                    unsigned long long bk = ~0ull;
                    #pragma unroll
                    for (int nt = 0; nt < 8; ++nt) {
                        const int lc = wn * 64 + nt * 8 + (lane & 3) * 2;
                        float2 cs = *(const float2*)(cq + lc);
                        float d0 = fmaf(-2.0f, acc[mt][nt][half * 2 + 0], cs.x);
                        float d1 = fmaf(-2.0f, acc[mt][nt][half * 2 + 1], cs.y);
                        unsigned long long k0 =
                            ((unsigned long long)enc_f32(d0) << 32) | (unsigned)lc;
                        unsigned long long k1 =
                            ((unsigned long long)enc_f32(d1) << 32) | (unsigned)(lc + 1);
                        unsigned long long km = k0 < k1 ? k0 : k1;
                        bk = km < bk ? km : bk;
                    }
                    unsigned long long o;
                    o = __shfl_xor_sync(0xFFFFFFFFu, bk, 1); bk = o < bk ? o : bk;
                    o = __shfl_xor_sync(0xFFFFFFFFu, bk, 2); bk = o < bk ? o : bk;
                    if ((lane & 3) == 0) {
                        const int row = m0 + wm * 32 + mt * 16 + half * 8 + (lane >> 2);
                        g_lmin2[((size_t)row * NT_TILES + ntile) * 2 + wn] =
                            (unsigned)(bk >> 32);
                    }
                }
            }
            #pragma unroll
            for (int i = 0; i < 2; ++i)
                #pragma unroll
                for (int j = 0; j < 8; ++j)
                    #pragma unroll
                    for (int c = 0; c < 4; ++c) acc[i][j][c] = 0.0f;
        }
    }
    #undef ISSUE_B
}

// ---------------- Phase 2: per-row exact rerank (coalesced) ----------------
__global__ void __launch_bounds__(128) rerank_kernel(
    const float* __restrict__ X, const float* __restrict__ Cc) {
    __shared__ __align__(16) float xs[D_DIM];
    __shared__ unsigned short cand[NT_TILES];
    __shared__ int ncand;
    __shared__ unsigned suw[4];
    __shared__ unsigned long long swarp[4];

    const int row = blockIdx.x;
    const int tid = threadIdx.x;
    const int lane = tid & 31;
    const int wid = tid >> 5;
    const int cg = lane >> 3;       // column group within warp (0..3)
    const int sl = lane & 7;        // sub-lane within group

    // tile mins: each uint2 = one tile's 2 warp-partials
    const uint2* lm2 = ((const uint2*)g_lmin2) + (size_t)row * NT_TILES;
    unsigned tmin[4];
    unsigned mn = 0xFFFFFFFFu;
    #pragma unroll
    for (int i = 0; i < 4; ++i) {
        uint2 k = lm2[tid + i * 128];
        tmin[i] = k.x < k.y ? k.x : k.y;
        mn = tmin[i] < mn ? tmin[i] : mn;
    }

    xs[tid] = X[(size_t)row * D_DIM + tid];
    xs[tid + 128] = X[(size_t)row * D_DIM + 128 + tid];
    if (tid == 0) ncand = 0;

    #pragma unroll
    for (int off = 16; off > 0; off >>= 1) {
        unsigned o = __shfl_xor_sync(0xFFFFFFFFu, mn, off);
        mn = o < mn ? o : mn;
    }
    if (lane == 0) suw[wid] = mn;
    __syncthreads();
    mn = suw[0];
    #pragma unroll
    for (int w = 1; w < 4; ++w) mn = suw[w] < mn ? suw[w] : mn;

    const unsigned thr_enc = enc_f32(dec_f32(mn) + M_MARGIN);

    #pragma unroll
    for (int i = 0; i < 4; ++i)
        if (tmin[i] <= thr_enc)
            cand[atomicAdd(&ncand, 1)] = tid + i * 128;
    __syncthreads();
    const int nc = ncand;

    // coalesced exact fp32: 4 cols per warp per pass (8 lanes per col)
    unsigned long long best = ~0ull;
    const float4* xp = (const float4*)xs;
    for (int i = 0; i < nc; ++i) {
        const int tbase = (int)cand[i] * BNT;
        #pragma unroll
        for (int p = 0; p < 8; ++p) {
            const int col = tbase + p * 16 + wid * 4 + cg;
            const float4* cp = (const float4*)(Cc + (size_t)col * D_DIM);
            float s = 0.f;
            #pragma unroll
            for (int j = 0; j < 8; ++j) {
                float4 v = cp[sl + j * 8];
                float4 u = xp[sl + j * 8];
                s = fmaf(v.x, u.x, s); s = fmaf(v.y, u.y, s);
                s = fmaf(v.z, u.z, s); s = fmaf(v.w, u.w, s);
            }
            s += __shfl_xor_sync(0xFFFFFFFFu, s, 1);
            s += __shfl_xor_sync(0xFFFFFFFFu, s, 2);
            s += __shfl_xor_sync(0xFFFFFFFFu, s, 4);
            if (sl == 0) {
                float dist = fmaf(-2.0f, s, __ldg(&g_csq[col]));
                unsigned long long key =
                    ((unsigned long long)enc_f32(dist) << 32) | (unsigned)col;
                best = key < best ? key : best;
            }
        }
    }

    // block-reduce best
    #pragma unroll
    for (int off = 16; off > 0; off >>= 1) {
        unsigned long long o = __shfl_xor_sync(0xFFFFFFFFu, best, off);
        best = o < best ? o : best;
    }
    if (lane == 0) swarp[wid] = best;
    __syncthreads();
    if (tid == 0) {
        unsigned long long b = swarp[0];
        #pragma unroll
        for (int w = 1; w < 4; ++w) b = swarp[w] < b ? swarp[w] : b;
        g_best[row] = b;
    }
}

// ---------------- gather winners + codes ----------------
__global__ void gather_kernel(const float* __restrict__ C, float* __restrict__ out,
                              int B) {
    int b = blockIdx.x;
    unsigned long long key = g_best[b];
    unsigned idx = (unsigned)(key & 0xFFFFFFFFull);
    const float* src = C + (size_t)idx * D_DIM;
    out[(size_t)b * D_DIM + threadIdx.x] = src[threadIdx.x];
    if (threadIdx.x == 0)
        out[(size_t)B * D_DIM + b] = (float)idx;
}

extern "C" void kernel_launch(void* const* d_in, const int* in_sizes, int n_in,
                              void* d_out, int out_size) {
    const float* x = (const float*)d_in[1];
    const float* cent = (const float*)d_in[2];
    const int B = in_sizes[1] / D_DIM;      // 4096
    const int K = in_sizes[2] / D_DIM;      // 65536
    float* out = (float*)d_out;

    static int smem_set = 0;
    if (!smem_set) {
        cudaFuncSetAttribute(gemm_approx_mma,
                             cudaFuncAttributeMaxDynamicSharedMemorySize, SMEM_DYN);
        smem_set = 1;
    }

    split_c_kernel<<<K / 8, 256>>>(cent);
    split_x_kernel<<<B / 8, 256>>>(x);
    const int grid = 32 * 32;                // m-tiles x n-groups = 1024
    gemm_approx_mma<<<grid, THREADS, SMEM_DYN>>>(0);
    rerank_kernel<<<B, 128>>>(x, cent);
    gather_kernel<<<B, D_DIM>>>(cent, out, B);
}

// round 17
// speedup vs baseline: 1.1428x; 1.1428x over previous
#include <cuda_runtime.h>
#include <cuda_fp16.h>
#include <cstdint>

// ============================================================
// IVFBook: dist = ||c||^2 - 2 x.c ; codes = argmin ; out = C[codes]
// B=4096, D=256, K=65536.
// Phase 1: 1-pass fp16 mma.sync approx GEMM (A-resident smem, B 8-stage
//          cp.async pipeline, sync every 4 chunks, KCH=64, csq in smem,
//          sync-free 32-bit per-warp epilogue -> g_lmin4[row][tile][wn]).
// Phase 2: per-row exact fp32 rerank of tiles within margin of the
//          global approx min (provably safe bound), coalesced.
// Output float32: [B*D quantized x][B codes-as-float]
// ============================================================

#define D_DIM 256
#define BMT 128          // CTA M tile
#define BNT 128          // N tile
#define KCH 64           // K chunk (fp16 elems) = 128B row
#define NCHT 4           // chunks per n-tile (D_DIM/KCH)
#define THREADS 512
#define ROWB 144         // B smem row stride (bytes): 36 words == 4 mod 32
#define ROWA 528         // A smem row stride (bytes)
#define NT_TILES 512     // K / BNT
#define NGT 16           // n-tiles per CTA
#define TOTCH (NGT * NCHT)  // 64 chunks per CTA
#define M_MARGIN 0.75f

#define A_BYTES (BMT * ROWA)      // 67584
#define B_STAGE (128 * ROWB)      // 18432
#define NSTAGE 8
#define CSQ_OFF (A_BYTES + NSTAGE * B_STAGE)          // 215040
#define SMEM_DYN (CSQ_OFF + NGT * BNT * 4)            // +8192 = 223232

__device__ unsigned long long g_best[4096];
__device__ unsigned g_lmin4[4096 * NT_TILES * 4];   // 32MB: 4 warp-partials/tile
__device__ float g_csq[65536];
__device__ __half g_c_hi[65536 * 256];
__device__ __half g_x_hi[4096 * 256];

__device__ __forceinline__ unsigned enc_f32(float f) {
    unsigned u = __float_as_uint(f);
    return (u & 0x80000000u) ? ~u : (u | 0x80000000u);
}
__device__ __forceinline__ float dec_f32(unsigned u) {
    unsigned v = (u & 0x80000000u) ? (u & 0x7FFFFFFFu) : ~u;
    return __uint_as_float(v);
}
__device__ __forceinline__ uint32_t smem_u32(const void* p) {
    uint32_t a;
    asm("{ .reg .u64 t; cvta.to.shared.u64 t, %1; cvt.u32.u64 %0, t; }"
        : "=r"(a) : "l"(p));
    return a;
}

#define LDSM4(r0, r1, r2, r3, addr) \
    asm volatile("ldmatrix.sync.aligned.m8n8.x4.shared.b16 {%0,%1,%2,%3}, [%4];" \
                 : "=r"(r0), "=r"(r1), "=r"(r2), "=r"(r3) : "r"(addr))

#define MMA_F16(d, a, b0, b1) \
    asm volatile( \
        "mma.sync.aligned.m16n8k16.row.col.f32.f16.f16.f32 " \
        "{%0,%1,%2,%3},{%4,%5,%6,%7},{%8,%9},{%0,%1,%2,%3};" \
        : "+f"((d)[0]), "+f"((d)[1]), "+f"((d)[2]), "+f"((d)[3]) \
        : "r"((a)[0]), "r"((a)[1]), "r"((a)[2]), "r"((a)[3]), \
          "r"(b0), "r"(b1))

#define CP16(dst, src) \
    asm volatile("cp.async.cg.shared.global [%0], [%1], 16;" \
                 :: "r"(dst), "l"(src) : "memory")
#define CP_COMMIT() asm volatile("cp.async.commit_group;" ::: "memory")
#define CP_WAIT3()  asm volatile("cp.async.wait_group 3;" ::: "memory")

// 8 floats -> 8 fp16
__device__ __forceinline__ uint4 pack8(float4 v0, float4 v1) {
    float f[8] = {v0.x, v0.y, v0.z, v0.w, v1.x, v1.y, v1.z, v1.w};
    unsigned hw[4];
    #pragma unroll
    for (int i = 0; i < 4; ++i) {
        __half h0 = __float2half_rn(f[2 * i]);
        __half h1 = __float2half_rn(f[2 * i + 1]);
        hw[i] = ((unsigned)__half_as_ushort(h1) << 16) | __half_as_ushort(h0);
    }
    return make_uint4(hw[0], hw[1], hw[2], hw[3]);
}

// ---------------- merged split: centroids(+csq) and x ----------------
__global__ void split_all_kernel(const float* __restrict__ C,
                                 const float* __restrict__ X, int ncb) {
    const int wid = threadIdx.x >> 5;
    const int lane = threadIdx.x & 31;
    if (blockIdx.x < ncb) {
        int row = blockIdx.x * 8 + wid;
        const float4* p = (const float4*)(C + (size_t)row * D_DIM + lane * 8);
        float4 v0 = p[0], v1 = p[1];
        *(uint4*)(g_c_hi + (size_t)row * D_DIM + lane * 8) = pack8(v0, v1);
        float s = v0.x * v0.x + v0.y * v0.y + v0.z * v0.z + v0.w * v0.w
                + v1.x * v1.x + v1.y * v1.y + v1.z * v1.z + v1.w * v1.w;
        #pragma unroll
        for (int off = 16; off > 0; off >>= 1)
            s += __shfl_xor_sync(0xFFFFFFFFu, s, off);
        if (lane == 0) g_csq[row] = s;
    } else {
        int row = (blockIdx.x - ncb) * 8 + wid;
        const float4* p = (const float4*)(X + (size_t)row * D_DIM + lane * 8);
        *(uint4*)(g_x_hi + (size_t)row * D_DIM + lane * 8) = pack8(p[0], p[1]);
    }
}

// ---------------- Phase 1: 1-pass approx GEMM, A resident ----------------
__global__ void __launch_bounds__(THREADS, 1) gemm_approx_mma(int dummy) {
    extern __shared__ __align__(16) unsigned char smraw[];

    const int tid = threadIdx.x;
    const int lane = tid & 31;
    const int wid = tid >> 5;
    const int wm = wid >> 2;        // 0..3 : m32 group
    const int wn = wid & 3;         // 0..3 : n32 group
    const int mt_idx = blockIdx.x & 31;
    const int ng = blockIdx.x >> 5;             // 0..31
    const int m0 = mt_idx * BMT;
    const int ntile0 = ng * NGT;

    const uint32_t sbA = smem_u32(smraw);
    const uint32_t sbB = sbA + A_BYTES;
    const uint32_t sbQ = sbA + CSQ_OFF;
    const float* cqs = (const float*)(smraw + CSQ_OFF);   // 2048 floats

    const int lrow = tid >> 2;          // 0..127
    const int lseg0 = tid & 3;          // 16B seg

    // ---- B chunk issue (two CP16 per thread: 128B per row) ----
    #define ISSUE_B(cidx) do { \
        const int _j = (cidx) >> 2, _kc = (cidx) & 3; \
        const __half* _src = g_c_hi + \
            (size_t)((ntile0 + _j) * BNT + lrow) * D_DIM + _kc * KCH + lseg0 * 8; \
        const uint32_t _dst = sbB + \
            (uint32_t)(((cidx) % NSTAGE) * B_STAGE + lrow * ROWB + lseg0 * 16); \
        CP16(_dst, _src); \
        CP16(_dst + 64, _src + 32); \
        CP_COMMIT(); \
    } while (0)

    // ---- group 0: A resident copy + csq + chunk 0 ----
    {
        const __half* aSrc = g_x_hi + (size_t)(m0 + lrow) * D_DIM;
        const uint32_t dA = sbA + (uint32_t)(lrow * ROWA);
        #pragma unroll
        for (int s = 0; s < 8; ++s) {
            const int seg = lseg0 + s * 4;
            CP16(dA + seg * 16, aSrc + seg * 8);
        }
        CP16(sbQ + tid * 16, g_csq + ntile0 * BNT + tid * 4);
        // chunk 0 into stage 0 (same commit group)
        const __half* b0 = g_c_hi + (size_t)(ntile0 * BNT + lrow) * D_DIM + lseg0 * 8;
        const uint32_t d0 = sbB + (uint32_t)(lrow * ROWB + lseg0 * 16);
        CP16(d0, b0);
        CP16(d0 + 64, b0 + 32);
        CP_COMMIT();
    }
    ISSUE_B(1); ISSUE_B(2); ISSUE_B(3);

    // ---- ldmatrix per-lane addresses (validated mapping) ----
    const uint32_t aRow = (uint32_t)((wm * 32 + (lane & 15)) * ROWA);
    const uint32_t aK   = (lane & 16) ? 16u : 0u;
    const uint32_t bRow = (uint32_t)((wn * 32 + (lane & 7) + ((lane & 16) >> 1)) * ROWB);
    const uint32_t bK   = (lane & 8) ? 16u : 0u;

    float acc[2][4][4];
    #pragma unroll
    for (int i = 0; i < 2; ++i)
        #pragma unroll
        for (int j = 0; j < 4; ++j)
            #pragma unroll
            for (int c = 0; c < 4; ++c) acc[i][j][c] = 0.0f;

    for (int cidx = 0; cidx < TOTCH; ++cidx) {
        CP_WAIT3();                       // chunk cidx complete
        if ((cidx & 3) == 0) __syncthreads();   // stage-reuse fence, every 4
        if (cidx + 4 < TOTCH) ISSUE_B(cidx + 4); else CP_COMMIT();

        const int kc = cidx & 3;
        const uint32_t stgB = sbB + (uint32_t)((cidx % NSTAGE) * B_STAGE);
        #pragma unroll
        for (int ks = 0; ks < 4; ++ks) {         // four k16 steps per chunk
            const uint32_t kBB = (uint32_t)(ks * 32);
            const uint32_t kBA = (uint32_t)(kc * 128 + ks * 32);
            unsigned ah[2][4], bh[2][4];
            #pragma unroll
            for (int mt = 0; mt < 2; ++mt) {
                uint32_t a = sbA + aRow + (uint32_t)(mt * 16 * ROWA) + kBA + aK;
                LDSM4(ah[mt][0], ah[mt][1], ah[mt][2], ah[mt][3], a);
            }
            #pragma unroll
            for (int np = 0; np < 2; ++np) {
                uint32_t b = stgB + bRow + (uint32_t)(np * 16 * ROWB) + kBB + bK;
                LDSM4(bh[np][0], bh[np][1], bh[np][2], bh[np][3], b);
            }
            #pragma unroll
            for (int mt = 0; mt < 2; ++mt)
                #pragma unroll
                for (int nt = 0; nt < 4; ++nt) {
                    const int np = nt >> 1, r = (nt & 1) * 2;
                    MMA_F16(acc[mt][nt], ah[mt], bh[np][r], bh[np][r + 1]);
                }
        }

        if (kc == NCHT - 1) {
            // ---- sync-free 32-bit epilogue: per-warp dist min -> g_lmin4 ----
            const int tileIdx = cidx >> 2;
            const int ntile = ntile0 + tileIdx;
            const float* cq = cqs + tileIdx * BNT;
            #pragma unroll
            for (int mt = 0; mt < 2; ++mt) {
                #pragma unroll
                for (int half = 0; half < 2; ++half) {
                    unsigned bk = 0xFFFFFFFFu;
                    #pragma unroll
                    for (int nt = 0; nt < 4; ++nt) {
                        const int lc = wn * 32 + nt * 8 + (lane & 3) * 2;
                        float2 cs = *(const float2*)(cq + lc);
                        float d0 = fmaf(-2.0f, acc[mt][nt][half * 2 + 0], cs.x);
                        float d1 = fmaf(-2.0f, acc[mt][nt][half * 2 + 1], cs.y);
                        unsigned e0 = enc_f32(d0);
                        unsigned e1 = enc_f32(d1);
                        unsigned em = e0 < e1 ? e0 : e1;
                        bk = em < bk ? em : bk;
                    }
                    unsigned o;
                    o = __shfl_xor_sync(0xFFFFFFFFu, bk, 1); bk = o < bk ? o : bk;
                    o = __shfl_xor_sync(0xFFFFFFFFu, bk, 2); bk = o < bk ? o : bk;
                    if ((lane & 3) == 0) {
                        const int row = m0 + wm * 32 + mt * 16 + half * 8 + (lane >> 2);
                        g_lmin4[((size_t)row * NT_TILES + ntile) * 4 + wn] = bk;
                    }
                }
            }
            #pragma unroll
            for (int i = 0; i < 2; ++i)
                #pragma unroll
                for (int j = 0; j < 4; ++j)
                    #pragma unroll
                    for (int c = 0; c < 4; ++c) acc[i][j][c] = 0.0f;
        }
    }
    #undef ISSUE_B
}

// ---------------- Phase 2: per-row exact rerank (coalesced) ----------------
__global__ void __launch_bounds__(128) rerank_kernel(
    const float* __restrict__ X, const float* __restrict__ Cc) {
    __shared__ __align__(16) float xs[D_DIM];
    __shared__ unsigned short cand[NT_TILES];
    __shared__ int ncand;
    __shared__ unsigned suw[4];
    __shared__ unsigned long long swarp[4];

    const int row = blockIdx.x;
    const int tid = threadIdx.x;
    const int lane = tid & 31;
    const int wid = tid >> 5;
    const int cg = lane >> 3;       // column group within warp (0..3)
    const int sl = lane & 7;        // sub-lane within group

    // tile mins: each uint4 = one tile's 4 warp-partials
    const uint4* lm4 = ((const uint4*)g_lmin4) + (size_t)row * NT_TILES;
    unsigned tmin[4];
    unsigned mn = 0xFFFFFFFFu;
    #pragma unroll
    for (int i = 0; i < 4; ++i) {
        uint4 k = lm4[tid + i * 128];
        unsigned a = k.x < k.y ? k.x : k.y;
        unsigned b = k.z < k.w ? k.z : k.w;
        tmin[i] = a < b ? a : b;
        mn = tmin[i] < mn ? tmin[i] : mn;
    }

    xs[tid] = X[(size_t)row * D_DIM + tid];
    xs[tid + 128] = X[(size_t)row * D_DIM + 128 + tid];
    if (tid == 0) ncand = 0;

    #pragma unroll
    for (int off = 16; off > 0; off >>= 1) {
        unsigned o = __shfl_xor_sync(0xFFFFFFFFu, mn, off);
        mn = o < mn ? o : mn;
    }
    if (lane == 0) suw[wid] = mn;
    __syncthreads();
    mn = suw[0];
    #pragma unroll
    for (int w = 1; w < 4; ++w) mn = suw[w] < mn ? suw[w] : mn;

    const unsigned thr_enc = enc_f32(dec_f32(mn) + M_MARGIN);

    #pragma unroll
    for (int i = 0; i < 4; ++i)
        if (tmin[i] <= thr_enc)
            cand[atomicAdd(&ncand, 1)] = tid + i * 128;
    __syncthreads();
    const int nc = ncand;

    // coalesced exact fp32: 4 cols per warp per pass (8 lanes per col)
    unsigned long long best = ~0ull;
    const float4* xp = (const float4*)xs;
    for (int i = 0; i < nc; ++i) {
        const int tbase = (int)cand[i] * BNT;
        #pragma unroll
        for (int p = 0; p < 8; ++p) {
            const int col = tbase + p * 16 + wid * 4 + cg;
            const float4* cp = (const float4*)(Cc + (size_t)col * D_DIM);
            float s = 0.f;
            #pragma unroll
            for (int j = 0; j < 8; ++j) {
                float4 v = cp[sl + j * 8];
                float4 u = xp[sl + j * 8];
                s = fmaf(v.x, u.x, s); s = fmaf(v.y, u.y, s);
                s = fmaf(v.z, u.z, s); s = fmaf(v.w, u.w, s);
            }
            s += __shfl_xor_sync(0xFFFFFFFFu, s, 1);
            s += __shfl_xor_sync(0xFFFFFFFFu, s, 2);
            s += __shfl_xor_sync(0xFFFFFFFFu, s, 4);
            if (sl == 0) {
                float dist = fmaf(-2.0f, s, __ldg(&g_csq[col]));
                unsigned long long key =
                    ((unsigned long long)enc_f32(dist) << 32) | (unsigned)col;
                best = key < best ? key : best;
            }
        }
    }

    // block-reduce best
    #pragma unroll
    for (int off = 16; off > 0; off >>= 1) {
        unsigned long long o = __shfl_xor_sync(0xFFFFFFFFu, best, off);
        best = o < best ? o : best;
    }
    if (lane == 0) swarp[wid] = best;
    __syncthreads();
    if (tid == 0) {
        unsigned long long b = swarp[0];
        #pragma unroll
        for (int w = 1; w < 4; ++w) b = swarp[w] < b ? swarp[w] : b;
        g_best[row] = b;
    }
}

// ---------------- gather winners + codes ----------------
__global__ void gather_kernel(const float* __restrict__ C, float* __restrict__ out,
                              int B) {
    int b = blockIdx.x;
    unsigned long long key = g_best[b];
    unsigned idx = (unsigned)(key & 0xFFFFFFFFull);
    const float* src = C + (size_t)idx * D_DIM;
    out[(size_t)b * D_DIM + threadIdx.x] = src[threadIdx.x];
    if (threadIdx.x == 0)
        out[(size_t)B * D_DIM + b] = (float)idx;
}

extern "C" void kernel_launch(void* const* d_in, const int* in_sizes, int n_in,
                              void* d_out, int out_size) {
    const float* x = (const float*)d_in[1];
    const float* cent = (const float*)d_in[2];
    const int B = in_sizes[1] / D_DIM;      // 4096
    const int K = in_sizes[2] / D_DIM;      // 65536
    float* out = (float*)d_out;

    static int smem_set = 0;
    if (!smem_set) {
        cudaFuncSetAttribute(gemm_approx_mma,
                             cudaFuncAttributeMaxDynamicSharedMemorySize, SMEM_DYN);
        smem_set = 1;
    }

    split_all_kernel<<<K / 8 + B / 8, 256>>>(cent, x, K / 8);
    const int grid = 32 * 32;                // m-tiles x n-groups = 1024
    gemm_approx_mma<<<grid, THREADS, SMEM_DYN>>>(0);
    rerank_kernel<<<B, 128>>>(x, cent);
    gather_kernel<<<B, D_DIM>>>(cent, out, B);
}